// round 3
// baseline (speedup 1.0000x reference)
#include <cuda_runtime.h>
#include <cuda_bf16.h>

// Problem constants (fixed shapes from reference)
#define D_MODEL 768
#define B_BATCH 8
#define L_SEQ   512
#define MAXW    12
#define N_SPANS (L_SEQ * MAXW)     // 6144
#define M_ROWS  (B_BATCH * L_SEQ)  // 4096

// Scratch: R = relu([h@Ws+bs | h@We+be])  (4096 x 1536)
//          PQ = [R_s @ Wo_top | R_e @ Wo_bot]  (4096 x 1536)
__device__ float g_R [M_ROWS * 2 * D_MODEL];
__device__ float g_PQ[M_ROWS * 2 * D_MODEL];

// ---------------------------------------------------------------------------
// Tiled fp32 SGEMM: C[M,N] = A[M,K] @ B[K,N] (+bias) (optional relu)
// BM=BN=128, BK=8, 256 threads, 8x8 per-thread microtile.
// All dims are multiples of tile sizes here, so no bounds checks.
// ---------------------------------------------------------------------------
#define BM 128
#define BN 128
#define BK 8
#define TM 8
#define TN 8

__global__ __launch_bounds__(256, 2)
void sgemm_kernel(const float* __restrict__ A, int lda,
                  const float* __restrict__ Bm, int ldb,
                  float* __restrict__ C, int ldc,
                  const float* __restrict__ bias, int relu, int K)
{
    __shared__ float As[BK][BM];
    __shared__ float Bs[BK][BN];

    const int tid  = threadIdx.x;
    const int row0 = blockIdx.y * BM;
    const int col0 = blockIdx.x * BN;

    const int tx = tid & 15;   // 0..15 -> N direction
    const int ty = tid >> 4;   // 0..15 -> M direction

    // A tile load: 128 rows x 8 cols; each thread one float4 along K
    const int aRow = tid >> 1;        // 0..127
    const int aCol = (tid & 1) * 4;   // 0 or 4
    // B tile load: 8 rows x 128 cols; each thread one float4 along N
    const int bRow = tid >> 5;        // 0..7
    const int bCol = (tid & 31) * 4;  // 0..124

    const float* Aptr = A  + (size_t)(row0 + aRow) * lda + aCol;
    const float* Bptr = Bm + (size_t)bRow * ldb + col0 + bCol;

    float acc[TM][TN];
#pragma unroll
    for (int i = 0; i < TM; i++)
#pragma unroll
        for (int j = 0; j < TN; j++) acc[i][j] = 0.0f;

    for (int k0 = 0; k0 < K; k0 += BK) {
        float4 av = *(const float4*)Aptr;  Aptr += BK;
        float4 bv = *(const float4*)Bptr;  Bptr += (size_t)BK * ldb;

        // store A transposed: As[k][m]
        As[aCol + 0][aRow] = av.x;
        As[aCol + 1][aRow] = av.y;
        As[aCol + 2][aRow] = av.z;
        As[aCol + 3][aRow] = av.w;
        *(float4*)&Bs[bRow][bCol] = bv;
        __syncthreads();

#pragma unroll
        for (int k = 0; k < BK; k++) {
            float a[TM], b[TN];
            float4 a0 = *(const float4*)&As[k][ty * TM];
            float4 a1 = *(const float4*)&As[k][ty * TM + 4];
            float4 b0 = *(const float4*)&Bs[k][tx * TN];
            float4 b1 = *(const float4*)&Bs[k][tx * TN + 4];
            a[0]=a0.x; a[1]=a0.y; a[2]=a0.z; a[3]=a0.w;
            a[4]=a1.x; a[5]=a1.y; a[6]=a1.z; a[7]=a1.w;
            b[0]=b0.x; b[1]=b0.y; b[2]=b0.z; b[3]=b0.w;
            b[4]=b1.x; b[5]=b1.y; b[6]=b1.z; b[7]=b1.w;
#pragma unroll
            for (int i = 0; i < TM; i++)
#pragma unroll
                for (int j = 0; j < TN; j++)
                    acc[i][j] = fmaf(a[i], b[j], acc[i][j]);
        }
        __syncthreads();
    }

    // Epilogue: optional bias + relu, float4 stores
#pragma unroll
    for (int i = 0; i < TM; i++) {
        const int r = row0 + ty * TM + i;
#pragma unroll
        for (int j = 0; j < TN; j += 4) {
            const int c = col0 + tx * TN + j;
            float4 v = make_float4(acc[i][j], acc[i][j+1], acc[i][j+2], acc[i][j+3]);
            if (bias) {
                v.x += bias[c + 0]; v.y += bias[c + 1];
                v.z += bias[c + 2]; v.w += bias[c + 3];
            }
            if (relu) {
                v.x = fmaxf(v.x, 0.0f); v.y = fmaxf(v.y, 0.0f);
                v.z = fmaxf(v.z, 0.0f); v.w = fmaxf(v.w, 0.0f);
            }
            *(float4*)&C[(size_t)r * ldc + c] = v;
        }
    }
}

// ---------------------------------------------------------------------------
// Gather epilogue: out[b, n, :] = P[b, is, :] + Q[b, ie, :] + bo
// One block per span, 192 threads x float4 = 768 floats.
// span_idx is INT32 (JAX x64 disabled canonicalizes int64 -> int32).
// Indices clamped defensively: no-op for valid data, finite rel_err (not a
// crash) if the dtype model is wrong.
// ---------------------------------------------------------------------------
__global__ __launch_bounds__(192)
void gather_kernel(const int* __restrict__ sidx,
                   const float* __restrict__ PQ,
                   const float* __restrict__ bo,
                   float* __restrict__ out)
{
    const int span = blockIdx.x;              // b * N_SPANS + n
    const int b    = span / N_SPANS;
    int is = sidx[(size_t)span * 2 + 0];
    int ie = sidx[(size_t)span * 2 + 1];
    is = min(max(is, 0), L_SEQ - 1);
    ie = min(max(ie, 0), L_SEQ - 1);

    const float* Prow = PQ + ((size_t)(b * L_SEQ + is)) * (2 * D_MODEL);
    const float* Qrow = PQ + ((size_t)(b * L_SEQ + ie)) * (2 * D_MODEL) + D_MODEL;
    float*       orow = out + (size_t)span * D_MODEL;

    const int d = threadIdx.x * 4;
    float4 p  = *(const float4*)(Prow + d);
    float4 q  = *(const float4*)(Qrow + d);
    float4 bb = *(const float4*)(bo + d);
    float4 r = make_float4(p.x + q.x + bb.x, p.y + q.y + bb.y,
                           p.z + q.z + bb.z, p.w + q.w + bb.w);
    *(float4*)(orow + d) = r;
}

// ---------------------------------------------------------------------------
extern "C" void kernel_launch(void* const* d_in, const int* in_sizes, int n_in,
                              void* d_out, int out_size)
{
    const float* h    = (const float*)d_in[0];
    const int*   sidx = (const int*)d_in[1];     // int32 (JAX canonicalized)
    const float* Ws   = (const float*)d_in[2];
    const float* bs   = (const float*)d_in[3];
    const float* We   = (const float*)d_in[4];
    const float* be   = (const float*)d_in[5];
    const float* Wo   = (const float*)d_in[6];
    const float* bo   = (const float*)d_in[7];
    float*       out  = (float*)d_out;

    float *R, *PQ;
    cudaGetSymbolAddress((void**)&R,  g_R);
    cudaGetSymbolAddress((void**)&PQ, g_PQ);

    const dim3 blk(256);
    const dim3 grd(D_MODEL / BN, M_ROWS / BM);   // (6, 32)

    // Stage 1: R = [relu(h@Ws+bs) | relu(h@We+be)]   (4096 x 1536)
    sgemm_kernel<<<grd, blk>>>(h, D_MODEL, Ws, D_MODEL,
                               R, 2 * D_MODEL, bs, 1, D_MODEL);
    sgemm_kernel<<<grd, blk>>>(h, D_MODEL, We, D_MODEL,
                               R + D_MODEL, 2 * D_MODEL, be, 1, D_MODEL);

    // Stage 2: PQ = [R_s @ Wo[:D] | R_e @ Wo[D:]]    (4096 x 1536)
    sgemm_kernel<<<grd, blk>>>(R, 2 * D_MODEL, Wo, D_MODEL,
                               PQ, 2 * D_MODEL, nullptr, 0, D_MODEL);
    sgemm_kernel<<<grd, blk>>>(R + D_MODEL, 2 * D_MODEL,
                               Wo + D_MODEL * D_MODEL, D_MODEL,
                               PQ + D_MODEL, 2 * D_MODEL, nullptr, 0, D_MODEL);

    // Stage 3: out[b,n,:] = PQ[b,is,:D] + PQ[b,ie,D:] + bo
    gather_kernel<<<B_BATCH * N_SPANS, 192>>>(sidx, PQ, bo, out);
}

// round 6
// speedup vs baseline: 2.2742x; 2.2742x over previous
#include <cuda_runtime.h>
#include <cuda_bf16.h>
#include <cstdint>

// ---------------------------------------------------------------------------
// Problem constants (fixed shapes)
// ---------------------------------------------------------------------------
#define D_MODEL 768
#define B_BATCH 8
#define L_SEQ   512
#define MAXW    12
#define N_SPANS (L_SEQ * MAXW)     // 6144
#define M_ROWS  (B_BATCH * L_SEQ)  // 4096

// ---------------------------------------------------------------------------
// Scratch (__device__ globals; no runtime allocation allowed)
// ---------------------------------------------------------------------------
__device__ __nv_bfloat16 g_h_hi [M_ROWS * D_MODEL];
__device__ __nv_bfloat16 g_h_lo [M_ROWS * D_MODEL];
__device__ __nv_bfloat16 g_WsT_hi[D_MODEL * D_MODEL];     // [N=768, K=768]
__device__ __nv_bfloat16 g_WsT_lo[D_MODEL * D_MODEL];
__device__ __nv_bfloat16 g_WeT_hi[D_MODEL * D_MODEL];
__device__ __nv_bfloat16 g_WeT_lo[D_MODEL * D_MODEL];
__device__ __nv_bfloat16 g_WoT_hi[D_MODEL * 2 * D_MODEL]; // [N=768, K=1536]
__device__ __nv_bfloat16 g_WoT_lo[D_MODEL * 2 * D_MODEL];
__device__ __nv_bfloat16 g_R_hi [M_ROWS * 2 * D_MODEL];   // relu(h@W+b), split
__device__ __nv_bfloat16 g_R_lo [M_ROWS * 2 * D_MODEL];
__device__ float         g_PQ   [M_ROWS * 2 * D_MODEL];   // fp32

// ---------------------------------------------------------------------------
// Baseline (non-'a') PTX helpers: cp.async + ldmatrix + mma.sync
// ---------------------------------------------------------------------------
__device__ __forceinline__ uint32_t smem_u32(const void* p) {
    uint32_t a;
    asm("{ .reg .u64 t; cvta.to.shared.u64 t, %1; cvt.u32.u64 %0, t; }"
        : "=r"(a) : "l"(p));
    return a;
}
__device__ __forceinline__ void cp_async16(uint32_t s, const void* g) {
    asm volatile("cp.async.cg.shared.global [%0], [%1], 16;" :: "r"(s), "l"(g));
}
__device__ __forceinline__ void cp_commit() {
    asm volatile("cp.async.commit_group;" ::: "memory");
}
template<int N> __device__ __forceinline__ void cp_wait() {
    asm volatile("cp.async.wait_group %0;" :: "n"(N) : "memory");
}
__device__ __forceinline__ void ldsm_x4(uint32_t* r, uint32_t a) {
    asm volatile("ldmatrix.sync.aligned.m8n8.x4.shared.b16 {%0,%1,%2,%3}, [%4];"
        : "=r"(r[0]), "=r"(r[1]), "=r"(r[2]), "=r"(r[3]) : "r"(a));
}
__device__ __forceinline__ void ldsm_x2(uint32_t* r, uint32_t a) {
    asm volatile("ldmatrix.sync.aligned.m8n8.x2.shared.b16 {%0,%1}, [%2];"
        : "=r"(r[0]), "=r"(r[1]) : "r"(a));
}
__device__ __forceinline__ void mma_bf16(float* d, const uint32_t* a, const uint32_t* b) {
    asm volatile("mma.sync.aligned.m16n8k16.row.col.f32.bf16.bf16.f32 "
        "{%0,%1,%2,%3}, {%4,%5,%6,%7}, {%8,%9}, {%0,%1,%2,%3};"
        : "+f"(d[0]), "+f"(d[1]), "+f"(d[2]), "+f"(d[3])
        : "r"(a[0]), "r"(a[1]), "r"(a[2]), "r"(a[3]), "r"(b[0]), "r"(b[1]));
}

// ---------------------------------------------------------------------------
// Prep 1: elementwise split fp32 -> (hi bf16, lo bf16)
// ---------------------------------------------------------------------------
__global__ void split4_kernel(const float4* __restrict__ x,
                              __nv_bfloat162* __restrict__ hi,
                              __nv_bfloat162* __restrict__ lo, int n4)
{
    int i = blockIdx.x * blockDim.x + threadIdx.x;
    if (i >= n4) return;
    float4 v = x[i];
    __nv_bfloat162 h0 = __floats2bfloat162_rn(v.x, v.y);
    __nv_bfloat162 h1 = __floats2bfloat162_rn(v.z, v.w);
    float rx = v.x - __low2float(h0),  ry = v.y - __high2float(h0);
    float rz = v.z - __low2float(h1),  rw = v.w - __high2float(h1);
    hi[2 * i]     = h0;
    hi[2 * i + 1] = h1;
    lo[2 * i]     = __floats2bfloat162_rn(rx, ry);
    lo[2 * i + 1] = __floats2bfloat162_rn(rz, rw);
}

// ---------------------------------------------------------------------------
// Prep 2: transpose + split. W [K,N] fp32 -> WT_hi/lo [N,K] bf16.
// ---------------------------------------------------------------------------
__global__ void transpose_split_kernel(const float* __restrict__ W, int K, int N,
                                       __nv_bfloat16* __restrict__ WT_hi,
                                       __nv_bfloat16* __restrict__ WT_lo)
{
    __shared__ float tile[32][33];
    const int n = blockIdx.x * 32 + threadIdx.x;
    const int k = blockIdx.y * 32 + threadIdx.y;
#pragma unroll
    for (int j = 0; j < 32; j += 8)
        tile[threadIdx.y + j][threadIdx.x] = W[(size_t)(k + j) * N + n];
    __syncthreads();
    const int k2 = blockIdx.y * 32 + threadIdx.x;
    const int n2 = blockIdx.x * 32 + threadIdx.y;
#pragma unroll
    for (int j = 0; j < 32; j += 8) {
        float v = tile[threadIdx.x][threadIdx.y + j];
        __nv_bfloat16 h = __float2bfloat16(v);
        float r = v - __bfloat162float(h);
        WT_hi[(size_t)(n2 + j) * K + k2] = h;
        WT_lo[(size_t)(n2 + j) * K + k2] = __float2bfloat16(r);
    }
}

// ---------------------------------------------------------------------------
// Split-bf16 tensor-core GEMM (mma.sync path, baseline PTX)
//   C[128x128 tile] = (Ah+Al) @ (Bh+Bl)^T  via 3 terms  Ah*Bh + Ah*Bl + Al*Bh
//   A: [M,K] K-major bf16 hi/lo.  B: [N,K] K-major bf16 hi/lo.
//   Output: fp32 (+bias/relu)  OR  split bf16 hi/lo (+bias/relu).
// 256 threads, warp grid 2(M)x4(N), warp tile 64x32, BK=32, double buffer.
// SMEM rows padded to 80 B -> ldmatrix conflict-free (5*row mod 8 permutation).
// ---------------------------------------------------------------------------
#define RSB     80                       // bytes per smem row (64 data + 16 pad)
#define TILE_B  (128 * RSB)              // 10240 B per operand tile
#define STAGE_B (4 * TILE_B)             // Ah, Al, Bh, Bl
#define GSMEM_BYTES (2 * STAGE_B)        // double buffered: 81920 B

__global__ void __launch_bounds__(256)
gemm_split_kernel(const __nv_bfloat16* __restrict__ Ah,
                  const __nv_bfloat16* __restrict__ Al, int lda,
                  const __nv_bfloat16* __restrict__ Bh,
                  const __nv_bfloat16* __restrict__ Bl, int ldb,
                  float* __restrict__ Cf,
                  __nv_bfloat16* __restrict__ Chi,
                  __nv_bfloat16* __restrict__ Clo, int ldc,
                  const float* __restrict__ bias, int doRelu, int K)
{
    extern __shared__ __align__(128) char smem[];
    const uint32_t sb = smem_u32(smem);
    const int tid  = threadIdx.x;
    const int wid  = tid >> 5;
    const int lane = tid & 31;
    const int m0 = blockIdx.y * 128, n0 = blockIdx.x * 128;

    const int m_w = (wid & 1) * 64;    // warp M offset in tile
    const int n_w = (wid >> 1) * 32;   // warp N offset in tile

    // ldmatrix per-lane address components
    const uint32_t a_row   = lane & 15;        // A: row within 16-row subtile
    const uint32_t a_chalf = lane >> 4;        // A: k half (0/1)
    const uint32_t b_row   = lane & 7;         // B: row within 8-row subtile
    const uint32_t b_chalf = (lane >> 3) & 1;  // B: k half

    float acc[4][4][4];
#pragma unroll
    for (int i = 0; i < 4; i++)
#pragma unroll
        for (int j = 0; j < 4; j++)
#pragma unroll
            for (int v = 0; v < 4; v++) acc[i][j][v] = 0.0f;

    const int nch = K / 32;

    // --- async tile loader: 4 tiles x 128 rows x 4 16B-chunks = 2048 chunks ---
    auto load_stage = [&](int kc, int buf) {
        const int k0 = kc * 32;
        const uint32_t sbase = sb + buf * STAGE_B;
#pragma unroll
        for (int i = 0; i < 8; i++) {
            const int cid  = tid + 256 * i;       // 0..2047
            const int tile = cid >> 9;            // 0:Ah 1:Al 2:Bh 3:Bl
            const int idx  = cid & 511;
            const int row  = idx >> 2;
            const int c    = idx & 3;
            const uint32_t saddr = sbase + tile * TILE_B + row * RSB + c * 16;
            const __nv_bfloat16* gp;
            if (tile < 2) {
                const __nv_bfloat16* base = (tile == 0) ? Ah : Al;
                gp = base + (size_t)(m0 + row) * lda + k0 + c * 8;
            } else {
                const __nv_bfloat16* base = (tile == 2) ? Bh : Bl;
                gp = base + (size_t)(n0 + row) * ldb + k0 + c * 8;
            }
            cp_async16(saddr, gp);
        }
        cp_commit();
    };

    load_stage(0, 0);

    for (int kc = 0; kc < nch; kc++) {
        if (kc + 1 < nch) load_stage(kc + 1, (kc + 1) & 1);
        if (kc + 1 < nch) cp_wait<1>(); else cp_wait<0>();
        __syncthreads();

        const uint32_t base = sb + (kc & 1) * STAGE_B;
#pragma unroll
        for (int kk = 0; kk < 2; kk++) {
            uint32_t ah[4][4], al[4][4], bh[4][2], bl[4][2];
            const uint32_t ac = (2 * kk + a_chalf) * 16;
            const uint32_t bc = (2 * kk + b_chalf) * 16;
#pragma unroll
            for (int mt = 0; mt < 4; mt++) {
                const uint32_t roff = (m_w + mt * 16 + a_row) * RSB + ac;
                ldsm_x4(ah[mt], base + 0 * TILE_B + roff);
                ldsm_x4(al[mt], base + 1 * TILE_B + roff);
            }
#pragma unroll
            for (int nt = 0; nt < 4; nt++) {
                const uint32_t roff = (n_w + nt * 8 + b_row) * RSB + bc;
                ldsm_x2(bh[nt], base + 2 * TILE_B + roff);
                ldsm_x2(bl[nt], base + 3 * TILE_B + roff);
            }
#pragma unroll
            for (int mt = 0; mt < 4; mt++)
#pragma unroll
                for (int nt = 0; nt < 4; nt++) {
                    mma_bf16(acc[mt][nt], ah[mt], bh[nt]);
                    mma_bf16(acc[mt][nt], ah[mt], bl[nt]);
                    mma_bf16(acc[mt][nt], al[mt], bh[nt]);
                }
        }
        __syncthreads();
    }

    // --- Epilogue: fragment layout m16n8 -> (row = lane/4 [+8], col = (lane%4)*2 [+1]) ---
    const int er = lane >> 2;
    const int ec = (lane & 3) * 2;
#pragma unroll
    for (int mt = 0; mt < 4; mt++) {
#pragma unroll
        for (int nt = 0; nt < 4; nt++) {
            const int col = n0 + n_w + nt * 8 + ec;
            const float b0 = bias ? bias[col]     : 0.0f;
            const float b1 = bias ? bias[col + 1] : 0.0f;
#pragma unroll
            for (int half = 0; half < 2; half++) {
                const int row = m0 + m_w + mt * 16 + er + half * 8;
                float v0 = acc[mt][nt][2 * half + 0] + b0;
                float v1 = acc[mt][nt][2 * half + 1] + b1;
                if (doRelu) { v0 = fmaxf(v0, 0.0f); v1 = fmaxf(v1, 0.0f); }
                if (Cf) {
                    *(float2*)&Cf[(size_t)row * ldc + col] = make_float2(v0, v1);
                } else {
                    __nv_bfloat162 h = __floats2bfloat162_rn(v0, v1);
                    float r0 = v0 - __low2float(h), r1 = v1 - __high2float(h);
                    __nv_bfloat162 l = __floats2bfloat162_rn(r0, r1);
                    const size_t o = (size_t)row * ldc + col;
                    *(__nv_bfloat162*)&Chi[o] = h;
                    *(__nv_bfloat162*)&Clo[o] = l;
                }
            }
        }
    }
}

// ---------------------------------------------------------------------------
// Gather epilogue: out[b,n,:] = PQ[b,is,:D] + PQ[b,ie,D:] + bo
// ---------------------------------------------------------------------------
__global__ __launch_bounds__(192)
void gather_kernel(const int* __restrict__ sidx,
                   const float* __restrict__ PQ,
                   const float* __restrict__ bo,
                   float* __restrict__ out)
{
    const int span = blockIdx.x;
    const int b    = span / N_SPANS;
    int is = sidx[(size_t)span * 2 + 0];
    int ie = sidx[(size_t)span * 2 + 1];
    is = min(max(is, 0), L_SEQ - 1);
    ie = min(max(ie, 0), L_SEQ - 1);

    const float* Prow = PQ + ((size_t)(b * L_SEQ + is)) * (2 * D_MODEL);
    const float* Qrow = PQ + ((size_t)(b * L_SEQ + ie)) * (2 * D_MODEL) + D_MODEL;
    float*       orow = out + (size_t)span * D_MODEL;

    const int d = threadIdx.x * 4;
    float4 p  = *(const float4*)(Prow + d);
    float4 q  = *(const float4*)(Qrow + d);
    float4 bb = *(const float4*)(bo + d);
    *(float4*)(orow + d) = make_float4(p.x + q.x + bb.x, p.y + q.y + bb.y,
                                       p.z + q.z + bb.z, p.w + q.w + bb.w);
}

// ---------------------------------------------------------------------------
extern "C" void kernel_launch(void* const* d_in, const int* in_sizes, int n_in,
                              void* d_out, int out_size)
{
    const float* h    = (const float*)d_in[0];
    const int*   sidx = (const int*)d_in[1];
    const float* Ws   = (const float*)d_in[2];
    const float* bs   = (const float*)d_in[3];
    const float* We   = (const float*)d_in[4];
    const float* be   = (const float*)d_in[5];
    const float* Wo   = (const float*)d_in[6];
    const float* bo   = (const float*)d_in[7];
    float*       out  = (float*)d_out;

    __nv_bfloat16 *h_hi, *h_lo, *WsT_hi, *WsT_lo, *WeT_hi, *WeT_lo;
    __nv_bfloat16 *WoT_hi, *WoT_lo, *R_hi, *R_lo;
    float* PQ;
    cudaGetSymbolAddress((void**)&h_hi,   g_h_hi);
    cudaGetSymbolAddress((void**)&h_lo,   g_h_lo);
    cudaGetSymbolAddress((void**)&WsT_hi, g_WsT_hi);
    cudaGetSymbolAddress((void**)&WsT_lo, g_WsT_lo);
    cudaGetSymbolAddress((void**)&WeT_hi, g_WeT_hi);
    cudaGetSymbolAddress((void**)&WeT_lo, g_WeT_lo);
    cudaGetSymbolAddress((void**)&WoT_hi, g_WoT_hi);
    cudaGetSymbolAddress((void**)&WoT_lo, g_WoT_lo);
    cudaGetSymbolAddress((void**)&R_hi,   g_R_hi);
    cudaGetSymbolAddress((void**)&R_lo,   g_R_lo);
    cudaGetSymbolAddress((void**)&PQ,     g_PQ);

    cudaFuncSetAttribute(gemm_split_kernel,
                         cudaFuncAttributeMaxDynamicSharedMemorySize, GSMEM_BYTES);

    // --- Prep: split h; transpose+split weights ---
    {
        const int n4 = (M_ROWS * D_MODEL) / 4;
        split4_kernel<<<(n4 + 255) / 256, 256>>>(
            (const float4*)h, (__nv_bfloat162*)h_hi, (__nv_bfloat162*)h_lo, n4);
        transpose_split_kernel<<<dim3(D_MODEL / 32, D_MODEL / 32), dim3(32, 8)>>>(
            Ws, D_MODEL, D_MODEL, WsT_hi, WsT_lo);
        transpose_split_kernel<<<dim3(D_MODEL / 32, D_MODEL / 32), dim3(32, 8)>>>(
            We, D_MODEL, D_MODEL, WeT_hi, WeT_lo);
        transpose_split_kernel<<<dim3(D_MODEL / 32, (2 * D_MODEL) / 32), dim3(32, 8)>>>(
            Wo, 2 * D_MODEL, D_MODEL, WoT_hi, WoT_lo);
    }

    const dim3 blk(256);
    const dim3 grd(D_MODEL / 128, M_ROWS / 128);   // (6, 32)

    // --- Stage 1: R = relu(h@Ws+bs) | relu(h@We+be), written as split bf16 ---
    gemm_split_kernel<<<grd, blk, GSMEM_BYTES>>>(
        h_hi, h_lo, D_MODEL, WsT_hi, WsT_lo, D_MODEL,
        nullptr, R_hi, R_lo, 2 * D_MODEL, bs, 1, D_MODEL);
    gemm_split_kernel<<<grd, blk, GSMEM_BYTES>>>(
        h_hi, h_lo, D_MODEL, WeT_hi, WeT_lo, D_MODEL,
        nullptr, R_hi + D_MODEL, R_lo + D_MODEL, 2 * D_MODEL, be, 1, D_MODEL);

    // --- Stage 2: PQ = [R_s @ Wo_top | R_e @ Wo_bot], fp32 ---
    gemm_split_kernel<<<grd, blk, GSMEM_BYTES>>>(
        R_hi, R_lo, 2 * D_MODEL, WoT_hi, WoT_lo, 2 * D_MODEL,
        PQ, nullptr, nullptr, 2 * D_MODEL, nullptr, 0, D_MODEL);
    gemm_split_kernel<<<grd, blk, GSMEM_BYTES>>>(
        R_hi + D_MODEL, R_lo + D_MODEL, 2 * D_MODEL,
        WoT_hi + D_MODEL, WoT_lo + D_MODEL, 2 * D_MODEL,
        PQ + D_MODEL, nullptr, nullptr, 2 * D_MODEL, nullptr, 0, D_MODEL);

    // --- Stage 3: gather ---
    gather_kernel<<<B_BATCH * N_SPANS, 192>>>(sidx, PQ, bo, out);
}